// round 13
// baseline (speedup 1.0000x reference)
#include <cuda_runtime.h>
#include <cuda_fp16.h>
#include <cstdint>
#include <cstddef>

// ----- problem dims -----
#define MDIM 8192
#define NDIM 16384
#define KDIM 4096

// ----- tiling -----
#define BM 128
#define BN 128
#define KC 64
#define NUM_KITER (KDIM / KC)      // 64
#define TILES_M (MDIM / BM)        // 64
#define TILES_N (NDIM / BN)        // 128
#define NCTA (TILES_M * TILES_N)   // 8192
#define GROUP_M 16

// packed sub-block: 128 rows x 64 K fp16 = 128 x 128B, SW128-swizzled smem image
#define SUB_BYTES 16384
#define A_OFF 0
#define B_OFF SUB_BYTES
#define STAGE_BYTES (2 * SUB_BYTES)    // 32768
#define NSTAGE 3
#define SMEM_DATA 1024
#define SMEM_TOTAL (SMEM_DATA + NSTAGE * STAGE_BYTES)   // 99328

#define SWZ128(x) ((x) ^ (((x) >> 3) & 0x70))

// ----- device scratch: packed fp16 images (128-row x 64-K sub-blocks) -----
__device__ __align__(1024) __half g_xp[(size_t)MDIM * KDIM];   //  64 MB
__device__ __align__(1024) __half g_wp[(size_t)NDIM * KDIM];   // 128 MB

// ----- helpers -----
__device__ __forceinline__ uint32_t smem_u32(const void* p) {
    uint32_t a;
    asm("{ .reg .u64 t; cvta.to.shared.u64 t, %1; cvt.u32.u64 %0, t; }" : "=r"(a) : "l"(p));
    return a;
}
__device__ __forceinline__ void mbar_init(uint32_t a, uint32_t cnt) {
    asm volatile("mbarrier.init.shared.b64 [%0], %1;" :: "r"(a), "r"(cnt) : "memory");
}
__device__ __forceinline__ void mbar_expect_tx(uint32_t a, uint32_t bytes) {
    asm volatile("mbarrier.arrive.expect_tx.shared.b64 _, [%0], %1;"
                 :: "r"(a), "r"(bytes) : "memory");
}
__device__ __forceinline__ void mbar_wait(uint32_t a, uint32_t parity) {
    uint32_t done;
    asm volatile(
        "{ .reg .pred p; mbarrier.try_wait.parity.acquire.cta.shared::cta.b64 p, [%1], %2; selp.b32 %0,1,0,p; }"
        : "=r"(done) : "r"(a), "r"(parity) : "memory");
    if (!done) {
        asm volatile(
            "{ .reg .pred P;\n"
            "WL_%=:\n"
            "mbarrier.try_wait.parity.acquire.cta.shared::cta.b64 P, [%0], %1, 0x989680;\n"
            "@P bra WD_%=;\n"
            "bra WL_%=;\n"
            "WD_%=: }"
            :: "r"(a), "r"(parity) : "memory");
    }
}
__device__ __forceinline__ void bulk_cp(uint32_t dst, const void* src, uint32_t bytes,
                                        uint32_t mbar) {
    asm volatile(
        "cp.async.bulk.shared::cluster.global.mbarrier::complete_tx::bytes [%0], [%1], %2, [%3];"
        :: "r"(dst), "l"(__cvta_generic_to_global(src)), "r"(bytes), "r"(mbar) : "memory");
}
__device__ __forceinline__ void ldsm4(uint32_t& r0, uint32_t& r1, uint32_t& r2, uint32_t& r3,
                                      uint32_t addr) {
    asm volatile("ldmatrix.sync.aligned.m8n8.x4.shared.b16 {%0,%1,%2,%3}, [%4];"
                 : "=r"(r0), "=r"(r1), "=r"(r2), "=r"(r3) : "r"(addr));
}
__device__ __forceinline__ void mma16816(float* c, const uint32_t* a, const uint32_t* b) {
    asm volatile(
        "mma.sync.aligned.m16n8k16.row.col.f32.f16.f16.f32 "
        "{%0,%1,%2,%3}, {%4,%5,%6,%7}, {%8,%9}, {%0,%1,%2,%3};"
        : "+f"(c[0]), "+f"(c[1]), "+f"(c[2]), "+f"(c[3])
        : "r"(a[0]), "r"(a[1]), "r"(a[2]), "r"(a[3]), "r"(b[0]), "r"(b[1]));
}

// ----- fused preprocessing (streaming hints; zero reuse) -----
__global__ void __launch_bounds__(256) k_pack(const int4* __restrict__ wq,
                                              const float4* __restrict__ x) {
    int b = blockIdx.x;
    if (b < 32768) {
        size_t t = (size_t)b * 256 + threadIdx.x;
        int o  = (int)(t >> 9);
        int k8 = (int)(t & 511);
        int4 a = __ldcs(wq + t * 2), bb = __ldcs(wq + t * 2 + 1);
        union { __half2 h[4]; uint4 u; } v;
        v.h[0] = __floats2half2_rn((float)a.x, (float)a.y);
        v.h[1] = __floats2half2_rn((float)a.z, (float)a.w);
        v.h[2] = __floats2half2_rn((float)bb.x, (float)bb.y);
        v.h[3] = __floats2half2_rn((float)bb.z, (float)bb.w);
        int tile = o >> 7, kk = k8 >> 3, c = k8 & 7;
        size_t base = ((size_t)(tile * (KDIM / 64) + kk)) * SUB_BYTES;
        uint32_t off = SWZ128((uint32_t)(((o & 127) << 7) + (c << 4)));
        __stcs((uint4*)((char*)g_wp + base + off), v.u);
    } else {
        size_t t = (size_t)(b - 32768) * 256 + threadIdx.x;
        int m  = (int)(t >> 9);
        int k8 = (int)(t & 511);
        float4 a = __ldcs(x + t * 2), bb = __ldcs(x + t * 2 + 1);
        union { __half2 h[4]; uint4 u; } v;
        v.h[0] = __floats2half2_rn(a.x, a.y);
        v.h[1] = __floats2half2_rn(a.z, a.w);
        v.h[2] = __floats2half2_rn(bb.x, bb.y);
        v.h[3] = __floats2half2_rn(bb.z, bb.w);
        int tile = m >> 7, kk = k8 >> 3, c = k8 & 7;
        size_t base = ((size_t)(tile * (KDIM / 64) + kk)) * SUB_BYTES;
        uint32_t off = SWZ128((uint32_t)(((m & 127) << 7) + (c << 4)));
        __stcs((uint4*)((char*)g_xp + base + off), v.u);
    }
}

// ----- main GEMM: 128x128 tile, 8 warps (4Mx2N), 2 CTAs/SM, K-rotation de-phasing -----
__global__ void __launch_bounds__(256, 2) k_gemm(const float* __restrict__ scale,
                                                 const float* __restrict__ bias,
                                                 float* __restrict__ out) {
    extern __shared__ char smem[];
    uint32_t sbase = smem_u32(smem);
    int tid = threadIdx.x, wid = tid >> 5, lane = tid & 31;

    // grouped rasterization for L2 reuse
    int bid   = blockIdx.x;
    int group = bid / (GROUP_M * TILES_N);
    int rem   = bid % (GROUP_M * TILES_N);
    int tm    = group * GROUP_M + (rem % GROUP_M);
    int tn    = rem / GROUP_M;

    // half-K rotation: co-resident CTAs (bid, bid+148) differ in bit 2 of bid,
    // so their chunk-boundary bubbles interleave instead of phase-locking.
    int koff = ((bid >> 2) & 1) * (NUM_KITER / 2);

    int wm = wid & 3;     // 32-row M sub-block
    int wn = wid >> 2;    // 64-col N sub-block

    const char* asrc = (const char*)g_xp + (size_t)tm * NUM_KITER * SUB_BYTES;
    const char* bsrc = (const char*)g_wp + (size_t)tn * NUM_KITER * SUB_BYTES;

    if (tid == 0) {
        mbar_init(sbase + 0, 1);
        mbar_init(sbase + 8, 1);
        mbar_init(sbase + 16, 1);
    }
    __syncthreads();

    // prologue: fill 3 stages (rotated chunk order)
    if (tid == 0) {
#pragma unroll
        for (int j = 0; j < NSTAGE; j++) {
            int kc = (j + koff) & (NUM_KITER - 1);
            uint32_t mb = sbase + j * 8;
            uint32_t st = sbase + SMEM_DATA + j * STAGE_BYTES;
            mbar_expect_tx(mb, STAGE_BYTES);
            bulk_cp(st + A_OFF, asrc + (size_t)kc * SUB_BYTES, SUB_BYTES, mb);
            bulk_cp(st + B_OFF, bsrc + (size_t)kc * SUB_BYTES, SUB_BYTES, mb);
        }
    }

    float acc[2][8][4];
#pragma unroll
    for (int i = 0; i < 2; i++)
#pragma unroll
        for (int j = 0; j < 8; j++)
#pragma unroll
            for (int k = 0; k < 4; k++) acc[i][j][k] = 0.f;

    // ldmatrix per-lane components
    int a_row = wm * 32 + (lane & 15);
    int a_cb  = (lane >> 4) * 16;
    int b_row = wn * 64 + ((lane >> 4) & 1) * 8 + (lane & 7);
    int b_cb  = ((lane >> 3) & 1) * 16;

    int stg = 0, phase = 0;
#pragma unroll 1
    for (int i = 0; i < NUM_KITER; i++) {
        uint32_t cur = sbase + SMEM_DATA + (uint32_t)stg * STAGE_BYTES;
        mbar_wait(sbase + stg * 8, (uint32_t)phase);

#pragma unroll
        for (int ks = 0; ks < 4; ks++) {
            int kc = ks * 32;
            uint32_t af[2][4], bf[8][2];
#pragma unroll
            for (int mf = 0; mf < 2; mf++) {
                uint32_t off = (uint32_t)((a_row + mf * 16) * 128 + a_cb + kc);
                ldsm4(af[mf][0], af[mf][1], af[mf][2], af[mf][3],
                      cur + A_OFF + SWZ128(off));
            }
#pragma unroll
            for (int nf2 = 0; nf2 < 4; nf2++) {
                uint32_t off = (uint32_t)((b_row + nf2 * 16) * 128 + b_cb + kc);
                ldsm4(bf[nf2 * 2][0], bf[nf2 * 2][1],
                      bf[nf2 * 2 + 1][0], bf[nf2 * 2 + 1][1],
                      cur + B_OFF + SWZ128(off));
            }
#pragma unroll
            for (int mf = 0; mf < 2; mf++)
#pragma unroll
                for (int nf = 0; nf < 8; nf++)
                    mma16816(acc[mf][nf], af[mf], bf[nf]);
        }
        __syncthreads();
        if (tid == 0 && i + NSTAGE < NUM_KITER) {
            int kc = (i + NSTAGE + koff) & (NUM_KITER - 1);
            uint32_t mb = sbase + stg * 8;
            mbar_expect_tx(mb, STAGE_BYTES);
            bulk_cp(cur + A_OFF, asrc + (size_t)kc * SUB_BYTES, SUB_BYTES, mb);
            bulk_cp(cur + B_OFF, bsrc + (size_t)kc * SUB_BYTES, SUB_BYTES, mb);
        }
        if (++stg == NSTAGE) { stg = 0; phase ^= 1; }
    }

    // ----- epilogue: y = acc * scale[n] + bias[n] -----
    int n_base = tn * BN + wn * 64 + (lane & 3) * 2;
    float sc[8][2], bi[8][2];
#pragma unroll
    for (int nf = 0; nf < 8; nf++) {
        int n = n_base + nf * 8;
        sc[nf][0] = scale[n];     sc[nf][1] = scale[n + 1];
        bi[nf][0] = bias[n];      bi[nf][1] = bias[n + 1];
    }
    int m_base = tm * BM + wm * 32 + (lane >> 2);
#pragma unroll
    for (int mf = 0; mf < 2; mf++) {
#pragma unroll
        for (int half = 0; half < 2; half++) {
            size_t row = (size_t)(m_base + mf * 16 + half * 8);
            float* orow = out + row * NDIM + n_base;
#pragma unroll
            for (int nf = 0; nf < 8; nf++) {
                float2 v;
                v.x = fmaf(acc[mf][nf][half * 2 + 0], sc[nf][0], bi[nf][0]);
                v.y = fmaf(acc[mf][nf][half * 2 + 1], sc[nf][1], bi[nf][1]);
                *(float2*)(orow + nf * 8) = v;
            }
        }
    }
}

extern "C" void kernel_launch(void* const* d_in, const int* in_sizes, int n_in,
                              void* d_out, int out_size) {
    const float* x     = (const float*)d_in[0];
    const int*   wq    = (const int*)d_in[1];
    const float* scale = (const float*)d_in[2];
    const float* bias  = (const float*)d_in[3];
    float* out = (float*)d_out;

    k_pack<<<49152, 256>>>((const int4*)wq, (const float4*)x);

    cudaFuncSetAttribute(k_gemm, cudaFuncAttributeMaxDynamicSharedMemorySize, SMEM_TOTAL);
    k_gemm<<<NCTA, 256, SMEM_TOTAL>>>(scale, bias, out);
}

// round 16
// speedup vs baseline: 1.0072x; 1.0072x over previous
#include <cuda_runtime.h>
#include <cuda_fp16.h>
#include <cstdint>
#include <cstddef>

// ----- problem dims -----
#define MDIM 8192
#define NDIM 16384
#define KDIM 4096

// ----- tiling -----
#define BM 128
#define BN 128
#define KC 64
#define NUM_KITER (KDIM / KC)      // 64
#define TILES_M (MDIM / BM)        // 64
#define TILES_N (NDIM / BN)        // 128
#define NCTA (TILES_M * TILES_N)   // 8192
#define GROUP_M 16

// packed sub-block: 128 rows x 64 K fp16 = 128 x 128B, SW128-swizzled smem image
#define SUB_BYTES 16384
#define A_OFF 0
#define B_OFF SUB_BYTES
#define STAGE_BYTES (2 * SUB_BYTES)    // 32768
#define NSTAGE 3
#define SMEM_DATA 1024
#define SMEM_TOTAL (SMEM_DATA + NSTAGE * STAGE_BYTES)   // 99328

#define SWZ128(x) ((x) ^ (((x) >> 3) & 0x70))

// ----- device scratch: packed fp16 images (128-row x 64-K sub-blocks) -----
__device__ __align__(1024) __half g_xp[(size_t)MDIM * KDIM];   //  64 MB
__device__ __align__(1024) __half g_wp[(size_t)NDIM * KDIM];   // 128 MB

// ----- helpers -----
__device__ __forceinline__ uint32_t smem_u32(const void* p) {
    uint32_t a;
    asm("{ .reg .u64 t; cvta.to.shared.u64 t, %1; cvt.u32.u64 %0, t; }" : "=r"(a) : "l"(p));
    return a;
}
__device__ __forceinline__ void mbar_init(uint32_t a, uint32_t cnt) {
    asm volatile("mbarrier.init.shared.b64 [%0], %1;" :: "r"(a), "r"(cnt) : "memory");
}
__device__ __forceinline__ void mbar_expect_tx(uint32_t a, uint32_t bytes) {
    asm volatile("mbarrier.arrive.expect_tx.shared.b64 _, [%0], %1;"
                 :: "r"(a), "r"(bytes) : "memory");
}
__device__ __forceinline__ void mbar_wait(uint32_t a, uint32_t parity) {
    uint32_t done;
    asm volatile(
        "{ .reg .pred p; mbarrier.try_wait.parity.acquire.cta.shared::cta.b64 p, [%1], %2; selp.b32 %0,1,0,p; }"
        : "=r"(done) : "r"(a), "r"(parity) : "memory");
    if (!done) {
        asm volatile(
            "{ .reg .pred P;\n"
            "WL_%=:\n"
            "mbarrier.try_wait.parity.acquire.cta.shared::cta.b64 P, [%0], %1, 0x989680;\n"
            "@P bra WD_%=;\n"
            "bra WL_%=;\n"
            "WD_%=: }"
            :: "r"(a), "r"(parity) : "memory");
    }
}
__device__ __forceinline__ void bulk_cp(uint32_t dst, const void* src, uint32_t bytes,
                                        uint32_t mbar) {
    asm volatile(
        "cp.async.bulk.shared::cluster.global.mbarrier::complete_tx::bytes [%0], [%1], %2, [%3];"
        :: "r"(dst), "l"(__cvta_generic_to_global(src)), "r"(bytes), "r"(mbar) : "memory");
}
__device__ __forceinline__ void ldsm4(uint32_t& r0, uint32_t& r1, uint32_t& r2, uint32_t& r3,
                                      uint32_t addr) {
    asm volatile("ldmatrix.sync.aligned.m8n8.x4.shared.b16 {%0,%1,%2,%3}, [%4];"
                 : "=r"(r0), "=r"(r1), "=r"(r2), "=r"(r3) : "r"(addr));
}
__device__ __forceinline__ void mma16816(float* c, const uint32_t* a, const uint32_t* b) {
    asm volatile(
        "mma.sync.aligned.m16n8k16.row.col.f32.f16.f16.f32 "
        "{%0,%1,%2,%3}, {%4,%5,%6,%7}, {%8,%9}, {%0,%1,%2,%3};"
        : "+f"(c[0]), "+f"(c[1]), "+f"(c[2]), "+f"(c[3])
        : "r"(a[0]), "r"(a[1]), "r"(a[2]), "r"(a[3]), "r"(b[0]), "r"(b[1]));
}

// ----- fused preprocessing (streaming hints; zero reuse) -----
__global__ void __launch_bounds__(256) k_pack(const int4* __restrict__ wq,
                                              const float4* __restrict__ x) {
    int b = blockIdx.x;
    if (b < 32768) {
        size_t t = (size_t)b * 256 + threadIdx.x;
        int o  = (int)(t >> 9);
        int k8 = (int)(t & 511);
        int4 a = __ldcs(wq + t * 2), bb = __ldcs(wq + t * 2 + 1);
        union { __half2 h[4]; uint4 u; } v;
        v.h[0] = __floats2half2_rn((float)a.x, (float)a.y);
        v.h[1] = __floats2half2_rn((float)a.z, (float)a.w);
        v.h[2] = __floats2half2_rn((float)bb.x, (float)bb.y);
        v.h[3] = __floats2half2_rn((float)bb.z, (float)bb.w);
        int tile = o >> 7, kk = k8 >> 3, c = k8 & 7;
        size_t base = ((size_t)(tile * (KDIM / 64) + kk)) * SUB_BYTES;
        uint32_t off = SWZ128((uint32_t)(((o & 127) << 7) + (c << 4)));
        __stcs((uint4*)((char*)g_wp + base + off), v.u);
    } else {
        size_t t = (size_t)(b - 32768) * 256 + threadIdx.x;
        int m  = (int)(t >> 9);
        int k8 = (int)(t & 511);
        float4 a = __ldcs(x + t * 2), bb = __ldcs(x + t * 2 + 1);
        union { __half2 h[4]; uint4 u; } v;
        v.h[0] = __floats2half2_rn(a.x, a.y);
        v.h[1] = __floats2half2_rn(a.z, a.w);
        v.h[2] = __floats2half2_rn(bb.x, bb.y);
        v.h[3] = __floats2half2_rn(bb.z, bb.w);
        int tile = m >> 7, kk = k8 >> 3, c = k8 & 7;
        size_t base = ((size_t)(tile * (KDIM / 64) + kk)) * SUB_BYTES;
        uint32_t off = SWZ128((uint32_t)(((m & 127) << 7) + (c << 4)));
        __stcs((uint4*)((char*)g_xp + base + off), v.u);
    }
}

// ----- main GEMM: 128x128 tile, 8 warps (4Mx2N, 32x64 warp tile), 2 CTAs/SM -----
__global__ void __launch_bounds__(256, 2) k_gemm(const float* __restrict__ scale,
                                                 const float* __restrict__ bias,
                                                 float* __restrict__ out) {
    extern __shared__ char smem[];
    uint32_t sbase = smem_u32(smem);
    int tid = threadIdx.x, wid = tid >> 5, lane = tid & 31;

    // grouped rasterization for L2 reuse
    int bid   = blockIdx.x;
    int group = bid / (GROUP_M * TILES_N);
    int rem   = bid % (GROUP_M * TILES_N);
    int tm    = group * GROUP_M + (rem % GROUP_M);
    int tn    = rem / GROUP_M;

    int wm = wid & 3;     // 32-row M sub-block
    int wn = wid >> 2;    // 64-col N sub-block

    const char* asrc = (const char*)g_xp + (size_t)tm * NUM_KITER * SUB_BYTES;
    const char* bsrc = (const char*)g_wp + (size_t)tn * NUM_KITER * SUB_BYTES;

    if (tid == 0) {
        mbar_init(sbase + 0, 1);
        mbar_init(sbase + 8, 1);
        mbar_init(sbase + 16, 1);
    }
    __syncthreads();

    // prologue: fill 3 stages
    if (tid == 0) {
#pragma unroll
        for (int j = 0; j < NSTAGE; j++) {
            uint32_t mb = sbase + j * 8;
            uint32_t st = sbase + SMEM_DATA + j * STAGE_BYTES;
            mbar_expect_tx(mb, STAGE_BYTES);
            bulk_cp(st + A_OFF, asrc + (size_t)j * SUB_BYTES, SUB_BYTES, mb);
            bulk_cp(st + B_OFF, bsrc + (size_t)j * SUB_BYTES, SUB_BYTES, mb);
        }
    }

    float acc[2][8][4];
#pragma unroll
    for (int i = 0; i < 2; i++)
#pragma unroll
        for (int j = 0; j < 8; j++)
#pragma unroll
            for (int k = 0; k < 4; k++) acc[i][j][k] = 0.f;

    // ldmatrix per-lane components
    int a_row = wm * 32 + (lane & 15);
    int a_cb  = (lane >> 4) * 16;
    int b_row = wn * 64 + ((lane >> 4) & 1) * 8 + (lane & 7);
    int b_cb  = ((lane >> 3) & 1) * 16;

    int stg = 0, phase = 0;
#pragma unroll 1
    for (int i = 0; i < NUM_KITER; i++) {
        uint32_t cur = sbase + SMEM_DATA + (uint32_t)stg * STAGE_BYTES;
        mbar_wait(sbase + stg * 8, (uint32_t)phase);

#pragma unroll
        for (int ks = 0; ks < 4; ks++) {
            int kc = ks * 32;
            uint32_t af[2][4], bf[8][2];
#pragma unroll
            for (int mf = 0; mf < 2; mf++) {
                uint32_t off = (uint32_t)((a_row + mf * 16) * 128 + a_cb + kc);
                ldsm4(af[mf][0], af[mf][1], af[mf][2], af[mf][3],
                      cur + A_OFF + SWZ128(off));
            }
#pragma unroll
            for (int nf2 = 0; nf2 < 4; nf2++) {
                uint32_t off = (uint32_t)((b_row + nf2 * 16) * 128 + b_cb + kc);
                ldsm4(bf[nf2 * 2][0], bf[nf2 * 2][1],
                      bf[nf2 * 2 + 1][0], bf[nf2 * 2 + 1][1],
                      cur + B_OFF + SWZ128(off));
            }
#pragma unroll
            for (int mf = 0; mf < 2; mf++)
#pragma unroll
                for (int nf = 0; nf < 8; nf++)
                    mma16816(acc[mf][nf], af[mf], bf[nf]);
        }
        __syncthreads();
        if (tid == 0 && i + NSTAGE < NUM_KITER) {
            uint32_t mb = sbase + stg * 8;
            mbar_expect_tx(mb, STAGE_BYTES);
            bulk_cp(cur + A_OFF, asrc + (size_t)(i + NSTAGE) * SUB_BYTES, SUB_BYTES, mb);
            bulk_cp(cur + B_OFF, bsrc + (size_t)(i + NSTAGE) * SUB_BYTES, SUB_BYTES, mb);
        }
        if (++stg == NSTAGE) { stg = 0; phase ^= 1; }
    }

    // ----- epilogue: y = acc * scale[n] + bias[n] -----
    int n_base = tn * BN + wn * 64 + (lane & 3) * 2;
    float sc[8][2], bi[8][2];
#pragma unroll
    for (int nf = 0; nf < 8; nf++) {
        int n = n_base + nf * 8;
        sc[nf][0] = scale[n];     sc[nf][1] = scale[n + 1];
        bi[nf][0] = bias[n];      bi[nf][1] = bias[n + 1];
    }
    int m_base = tm * BM + wm * 32 + (lane >> 2);
#pragma unroll
    for (int mf = 0; mf < 2; mf++) {
#pragma unroll
        for (int half = 0; half < 2; half++) {
            size_t row = (size_t)(m_base + mf * 16 + half * 8);
            float* orow = out + row * NDIM + n_base;
#pragma unroll
            for (int nf = 0; nf < 8; nf++) {
                float2 v;
                v.x = fmaf(acc[mf][nf][half * 2 + 0], sc[nf][0], bi[nf][0]);
                v.y = fmaf(acc[mf][nf][half * 2 + 1], sc[nf][1], bi[nf][1]);
                *(float2*)(orow + nf * 8) = v;
            }
        }
    }
}

extern "C" void kernel_launch(void* const* d_in, const int* in_sizes, int n_in,
                              void* d_out, int out_size) {
    const float* x     = (const float*)d_in[0];
    const int*   wq    = (const int*)d_in[1];
    const float* scale = (const float*)d_in[2];
    const float* bias  = (const float*)d_in[3];
    float* out = (float*)d_out;

    k_pack<<<49152, 256>>>((const int4*)wq, (const float4*)x);

    cudaFuncSetAttribute(k_gemm, cudaFuncAttributeMaxDynamicSharedMemorySize, SMEM_TOTAL);
    k_gemm<<<NCTA, 256, SMEM_TOTAL>>>(scale, bias, out);
}

// round 17
// speedup vs baseline: 1.0092x; 1.0019x over previous
#include <cuda_runtime.h>
#include <cuda_fp16.h>
#include <cstdint>
#include <cstddef>

// ----- problem dims -----
#define MDIM 8192
#define NDIM 16384
#define KDIM 4096

// ----- tiling -----
#define BM 128
#define BN 128
#define KC 64
#define NUM_KITER (KDIM / KC)      // 64
#define TILES_M (MDIM / BM)        // 64
#define TILES_N (NDIM / BN)        // 128
#define NCTA (TILES_M * TILES_N)   // 8192
#define GROUP_M 16

// packed sub-block: 128 rows x 64 K fp16 = 128 x 128B, SW128-swizzled smem image
#define SUB_BYTES 16384
#define A_OFF 0
#define B_OFF SUB_BYTES
#define STAGE_BYTES (2 * SUB_BYTES)    // 32768
#define NSTAGE 3
#define SMEM_DATA 1024
#define SMEM_TOTAL (SMEM_DATA + NSTAGE * STAGE_BYTES)   // 99328

#define SWZ128(x) ((x) ^ (((x) >> 3) & 0x70))

// ----- device scratch: packed fp16 images (128-row x 64-K sub-blocks) -----
__device__ __align__(1024) __half g_xp[(size_t)MDIM * KDIM];   //  64 MB
__device__ __align__(1024) __half g_wp[(size_t)NDIM * KDIM];   // 128 MB

// ----- helpers -----
__device__ __forceinline__ uint32_t smem_u32(const void* p) {
    uint32_t a;
    asm("{ .reg .u64 t; cvta.to.shared.u64 t, %1; cvt.u32.u64 %0, t; }" : "=r"(a) : "l"(p));
    return a;
}
__device__ __forceinline__ void mbar_init(uint32_t a, uint32_t cnt) {
    asm volatile("mbarrier.init.shared.b64 [%0], %1;" :: "r"(a), "r"(cnt) : "memory");
}
__device__ __forceinline__ void mbar_expect_tx(uint32_t a, uint32_t bytes) {
    asm volatile("mbarrier.arrive.expect_tx.shared.b64 _, [%0], %1;"
                 :: "r"(a), "r"(bytes) : "memory");
}
__device__ __forceinline__ void mbar_wait(uint32_t a, uint32_t parity) {
    uint32_t done;
    asm volatile(
        "{ .reg .pred p; mbarrier.try_wait.parity.acquire.cta.shared::cta.b64 p, [%1], %2; selp.b32 %0,1,0,p; }"
        : "=r"(done) : "r"(a), "r"(parity) : "memory");
    if (!done) {
        asm volatile(
            "{ .reg .pred P;\n"
            "WL_%=:\n"
            "mbarrier.try_wait.parity.acquire.cta.shared::cta.b64 P, [%0], %1, 0x989680;\n"
            "@P bra WD_%=;\n"
            "bra WL_%=;\n"
            "WD_%=: }"
            :: "r"(a), "r"(parity) : "memory");
    }
}
__device__ __forceinline__ void bulk_cp(uint32_t dst, const void* src, uint32_t bytes,
                                        uint32_t mbar) {
    asm volatile(
        "cp.async.bulk.shared::cluster.global.mbarrier::complete_tx::bytes [%0], [%1], %2, [%3];"
        :: "r"(dst), "l"(__cvta_generic_to_global(src)), "r"(bytes), "r"(mbar) : "memory");
}
__device__ __forceinline__ void ldsm4(uint32_t& r0, uint32_t& r1, uint32_t& r2, uint32_t& r3,
                                      uint32_t addr) {
    asm volatile("ldmatrix.sync.aligned.m8n8.x4.shared.b16 {%0,%1,%2,%3}, [%4];"
                 : "=r"(r0), "=r"(r1), "=r"(r2), "=r"(r3) : "r"(addr));
}
__device__ __forceinline__ void mma16816(float* c, const uint32_t* a, const uint32_t* b) {
    asm volatile(
        "mma.sync.aligned.m16n8k16.row.col.f32.f16.f16.f32 "
        "{%0,%1,%2,%3}, {%4,%5,%6,%7}, {%8,%9}, {%0,%1,%2,%3};"
        : "+f"(c[0]), "+f"(c[1]), "+f"(c[2]), "+f"(c[3])
        : "r"(a[0]), "r"(a[1]), "r"(a[2]), "r"(a[3]), "r"(b[0]), "r"(b[1]));
}

// ----- fused preprocessing (streaming hints; zero reuse) -----
__global__ void __launch_bounds__(256) k_pack(const int4* __restrict__ wq,
                                              const float4* __restrict__ x) {
    int b = blockIdx.x;
    if (b < 32768) {
        size_t t = (size_t)b * 256 + threadIdx.x;
        int o  = (int)(t >> 9);
        int k8 = (int)(t & 511);
        int4 a = __ldcs(wq + t * 2), bb = __ldcs(wq + t * 2 + 1);
        union { __half2 h[4]; uint4 u; } v;
        v.h[0] = __floats2half2_rn((float)a.x, (float)a.y);
        v.h[1] = __floats2half2_rn((float)a.z, (float)a.w);
        v.h[2] = __floats2half2_rn((float)bb.x, (float)bb.y);
        v.h[3] = __floats2half2_rn((float)bb.z, (float)bb.w);
        int tile = o >> 7, kk = k8 >> 3, c = k8 & 7;
        size_t base = ((size_t)(tile * (KDIM / 64) + kk)) * SUB_BYTES;
        uint32_t off = SWZ128((uint32_t)(((o & 127) << 7) + (c << 4)));
        __stcs((uint4*)((char*)g_wp + base + off), v.u);
    } else {
        size_t t = (size_t)(b - 32768) * 256 + threadIdx.x;
        int m  = (int)(t >> 9);
        int k8 = (int)(t & 511);
        float4 a = __ldcs(x + t * 2), bb = __ldcs(x + t * 2 + 1);
        union { __half2 h[4]; uint4 u; } v;
        v.h[0] = __floats2half2_rn(a.x, a.y);
        v.h[1] = __floats2half2_rn(a.z, a.w);
        v.h[2] = __floats2half2_rn(bb.x, bb.y);
        v.h[3] = __floats2half2_rn(bb.z, bb.w);
        int tile = m >> 7, kk = k8 >> 3, c = k8 & 7;
        size_t base = ((size_t)(tile * (KDIM / 64) + kk)) * SUB_BYTES;
        uint32_t off = SWZ128((uint32_t)(((m & 127) << 7) + (c << 4)));
        __stcs((uint4*)((char*)g_xp + base + off), v.u);
    }
}

// ----- main GEMM: 128x128 tile, 8 warps (4Mx2N, 32x64 warp tile), 2 CTAs/SM -----
__global__ void __launch_bounds__(256, 2) k_gemm(const float* __restrict__ scale,
                                                 const float* __restrict__ bias,
                                                 float* __restrict__ out) {
    extern __shared__ char smem[];
    uint32_t sbase = smem_u32(smem);
    int tid = threadIdx.x, wid = tid >> 5, lane = tid & 31;

    // grouped rasterization for L2 reuse
    int bid   = blockIdx.x;
    int group = bid / (GROUP_M * TILES_N);
    int rem   = bid % (GROUP_M * TILES_N);
    int tm    = group * GROUP_M + (rem % GROUP_M);
    int tn    = rem / GROUP_M;

    int wm = wid & 3;     // 32-row M sub-block
    int wn = wid >> 2;    // 64-col N sub-block

    const char* asrc = (const char*)g_xp + (size_t)tm * NUM_KITER * SUB_BYTES;
    const char* bsrc = (const char*)g_wp + (size_t)tn * NUM_KITER * SUB_BYTES;

    if (tid == 0) {
        mbar_init(sbase + 0, 1);
        mbar_init(sbase + 8, 1);
        mbar_init(sbase + 16, 1);
    }
    __syncthreads();

    // prologue: fill 3 stages
    if (tid == 0) {
#pragma unroll
        for (int j = 0; j < NSTAGE; j++) {
            uint32_t mb = sbase + j * 8;
            uint32_t st = sbase + SMEM_DATA + j * STAGE_BYTES;
            mbar_expect_tx(mb, STAGE_BYTES);
            bulk_cp(st + A_OFF, asrc + (size_t)j * SUB_BYTES, SUB_BYTES, mb);
            bulk_cp(st + B_OFF, bsrc + (size_t)j * SUB_BYTES, SUB_BYTES, mb);
        }
    }

    float acc[2][8][4];
#pragma unroll
    for (int i = 0; i < 2; i++)
#pragma unroll
        for (int j = 0; j < 8; j++)
#pragma unroll
            for (int k = 0; k < 4; k++) acc[i][j][k] = 0.f;

    // ldmatrix per-lane components
    int a_row = wm * 32 + (lane & 15);
    int a_cb  = (lane >> 4) * 16;
    int b_row = wn * 64 + ((lane >> 4) & 1) * 8 + (lane & 7);
    int b_cb  = ((lane >> 3) & 1) * 16;

    int stg = 0, phase = 0;
#pragma unroll 1
    for (int i = 0; i < NUM_KITER; i++) {
        uint32_t cur = sbase + SMEM_DATA + (uint32_t)stg * STAGE_BYTES;
        mbar_wait(sbase + stg * 8, (uint32_t)phase);

#pragma unroll
        for (int ks = 0; ks < 4; ks++) {
            int kc = ks * 32;
            uint32_t af[2][4], bf[8][2];
#pragma unroll
            for (int mf = 0; mf < 2; mf++) {
                uint32_t off = (uint32_t)((a_row + mf * 16) * 128 + a_cb + kc);
                ldsm4(af[mf][0], af[mf][1], af[mf][2], af[mf][3],
                      cur + A_OFF + SWZ128(off));
            }
#pragma unroll
            for (int nf2 = 0; nf2 < 4; nf2++) {
                uint32_t off = (uint32_t)((b_row + nf2 * 16) * 128 + b_cb + kc);
                ldsm4(bf[nf2 * 2][0], bf[nf2 * 2][1],
                      bf[nf2 * 2 + 1][0], bf[nf2 * 2 + 1][1],
                      cur + B_OFF + SWZ128(off));
            }
#pragma unroll
            for (int mf = 0; mf < 2; mf++)
#pragma unroll
                for (int nf = 0; nf < 8; nf++)
                    mma16816(acc[mf][nf], af[mf], bf[nf]);
        }
        __syncthreads();
        if (tid == 0 && i + NSTAGE < NUM_KITER) {
            uint32_t mb = sbase + stg * 8;
            mbar_expect_tx(mb, STAGE_BYTES);
            bulk_cp(cur + A_OFF, asrc + (size_t)(i + NSTAGE) * SUB_BYTES, SUB_BYTES, mb);
            bulk_cp(cur + B_OFF, bsrc + (size_t)(i + NSTAGE) * SUB_BYTES, SUB_BYTES, mb);
        }
        if (++stg == NSTAGE) { stg = 0; phase ^= 1; }
    }

    // ----- epilogue: y = acc * scale[n] + bias[n] -----
    int n_base = tn * BN + wn * 64 + (lane & 3) * 2;
    float sc[8][2], bi[8][2];
#pragma unroll
    for (int nf = 0; nf < 8; nf++) {
        int n = n_base + nf * 8;
        sc[nf][0] = scale[n];     sc[nf][1] = scale[n + 1];
        bi[nf][0] = bias[n];      bi[nf][1] = bias[n + 1];
    }
    int m_base = tm * BM + wm * 32 + (lane >> 2);
#pragma unroll
    for (int mf = 0; mf < 2; mf++) {
#pragma unroll
        for (int half = 0; half < 2; half++) {
            size_t row = (size_t)(m_base + mf * 16 + half * 8);
            float* orow = out + row * NDIM + n_base;
#pragma unroll
            for (int nf = 0; nf < 8; nf++) {
                float2 v;
                v.x = fmaf(acc[mf][nf][half * 2 + 0], sc[nf][0], bi[nf][0]);
                v.y = fmaf(acc[mf][nf][half * 2 + 1], sc[nf][1], bi[nf][1]);
                *(float2*)(orow + nf * 8) = v;
            }
        }
    }
}

extern "C" void kernel_launch(void* const* d_in, const int* in_sizes, int n_in,
                              void* d_out, int out_size) {
    const float* x     = (const float*)d_in[0];
    const int*   wq    = (const int*)d_in[1];
    const float* scale = (const float*)d_in[2];
    const float* bias  = (const float*)d_in[3];
    float* out = (float*)d_out;

    k_pack<<<49152, 256>>>((const int4*)wq, (const float4*)x);

    cudaFuncSetAttribute(k_gemm, cudaFuncAttributeMaxDynamicSharedMemorySize, SMEM_TOTAL);
    k_gemm<<<NCTA, 256, SMEM_TOTAL>>>(scale, bias, out);
}